// round 16
// baseline (speedup 1.0000x reference)
#include <cuda_runtime.h>
#include <math.h>

// B=2, DIM=32, H=W=512, FOLD=8, P=2, HDIM=96, NCLS=16, CV=96
// S=4, tile 64x64, N=4096 px/tile, 128 tiles.
// out: center_feat [2,256,96]=49152 | labels [2,16,256]=8192 | spix_map [2,512,512]=524288

struct SmemLayout {
    float4 scst[4096];    // per-pixel static (x+sdf) scores
    float4 a4[2][1024];   // double-buffered per-chunk weights
    float4 cen4[160];     // pooled quadrant means: x[0..31], sdf[32..62], feat[63..158]
    float4 cdf4[96];
    float4 csf4[96];
    float4 g4[32];
    float4 q4[32];
    float4 cpf1[96];
    float4 num4[96];
    float4 onum4[96];
    float Cs[4], n0[4], n1[4], den[4], wden[4];
    int   cnt[4][16];
};

__device__ __forceinline__ float wredsum(float v) {
#pragma unroll
    for (int o = 16; o; o >>= 1) v += __shfl_xor_sync(0xffffffffu, v, o);
    return v;
}

__global__ void __launch_bounds__(1024, 1)
cluster_kernel(const float* __restrict__ x, const float* __restrict__ feat,
               const float* __restrict__ sdf, const float* __restrict__ Wf,
               const float* __restrict__ bf, const float* __restrict__ Wsdf,
               const float* __restrict__ bsdf, const int* __restrict__ gt,
               float* __restrict__ out)
{
    extern __shared__ char smem_raw[];
    SmemLayout* sh = reinterpret_cast<SmemLayout*>(smem_raw);

    const int tile = blockIdx.x;
    const int b    = tile >> 6;
    const int f1   = (tile >> 3) & 7;
    const int f2   = tile & 7;
    const int tid  = threadIdx.x;
    const int wid  = tid >> 5;
    const int lane = tid & 31;
    const int base = f1 * 64 * 512 + f2 * 64;

    if (tid < 4) { sh->den[tid] = 0.f; sh->wden[tid] = 0.f; }
    if (tid < 64) sh->cnt[tid >> 4][tid & 15] = 0;

    // ---------------- Phase 1: quadrant pooling (float4) ----------------
    for (int ch = wid; ch < 159; ch += 32) {
        const float* src;
        if (ch < 32)      src = x    + (((size_t)(b * 32 + ch)) << 18);
        else if (ch < 63) src = sdf  + (((size_t)(b * 31 + (ch - 32))) << 18);
        else              src = feat + (((size_t)(b * 96 + (ch - 63))) << 18);
        src += base;
        float acc[4];
#pragma unroll
        for (int q = 0; q < 4; q++) {
            const float* p2 = src + (q >> 1) * 32 * 512 + (q & 1) * 32
                                  + (lane >> 3) * 512 + (lane & 7) * 4;
            float a = 0.f;
#pragma unroll
            for (int i = 0; i < 8; i++) {
                float4 v = *(const float4*)(p2 + i * 4 * 512);
                a += (v.x + v.y) + (v.z + v.w);
            }
            acc[q] = a;
        }
#pragma unroll
        for (int q = 0; q < 4; q++) acc[q] = wredsum(acc[q]);
        if (lane == 0)
            sh->cen4[ch] = make_float4(acc[0] * (1.f / 1024.f), acc[1] * (1.f / 1024.f),
                                       acc[2] * (1.f / 1024.f), acc[3] * (1.f / 1024.f));
    }
    __syncthreads();

    // ---------------- Phase 2: per-tile derived quantities ----------------
    if (tid < 384) {
        int j = tid >> 2, s = tid & 3;
        const float* wr = Wf + j * 32;
        float a = bf[j];
#pragma unroll 8
        for (int c = 0; c < 32; c++) a = fmaf(wr[c], ((const float*)&sh->cen4[c])[s], a);
        ((float*)&sh->cdf4[j])[s] = a;
        const float* wr2 = Wsdf + j * 31;
        float a2 = bsdf[j];
#pragma unroll 8
        for (int c = 0; c < 31; c++) a2 = fmaf(wr2[c], ((const float*)&sh->cen4[32 + c])[s], a2);
        ((float*)&sh->csf4[j])[s] = a2;
    }
    __syncthreads();
    if (tid < 128) {
        int c = tid >> 2, s = tid & 3;
        float a = 0.f;
        for (int j = 0; j < 96; j++) a = fmaf(Wf[j * 32 + c], ((const float*)&sh->cdf4[j])[s], a);
        ((float*)&sh->g4[c])[s] = a;
    } else if (tid < 252) {
        int t2 = tid - 128; int c = t2 >> 2, s = t2 & 3;
        float a = 0.f;
        for (int j = 0; j < 96; j++) a = fmaf(Wsdf[j * 31 + c], ((const float*)&sh->csf4[j])[s], a);
        ((float*)&sh->q4[c])[s] = a;
    } else if (tid >= 256 && tid < 260) {
        int s = tid - 256;
        float kf = 0.f, ks = 0.f, nd = 0.f, ns = 0.f;
        for (int j = 0; j < 96; j++) {
            float d = ((const float*)&sh->cdf4[j])[s];
            float e = ((const float*)&sh->csf4[j])[s];
            kf = fmaf(bf[j], d, kf); ks = fmaf(bsdf[j], e, ks);
            nd = fmaf(d, d, nd);     ns = fmaf(e, e, ns);
        }
        sh->Cs[s] = 2.f * kf + 2.f * ks - nd - ns;
    } else if (tid >= 260 && tid < 264) {
        int s = tid - 260;
        float a = 0.f;
        for (int c = 0; c < 96; c++) { float v = ((const float*)&sh->cen4[63 + c])[s]; a = fmaf(v, v, a); }
        sh->n0[s] = a;
    }
    __syncthreads();

    const float C0 = sh->Cs[0], C1 = sh->Cs[1], C2 = sh->Cs[2], C3 = sh->Cs[3];
    const float m0 = sh->n0[0], m1 = sh->n0[1], m2 = sh->n0[2], m3 = sh->n0[3];

    const float* xb = x    + (((size_t)(b * 32)) << 18) + base;
    const float* sb = sdf  + (((size_t)(b * 31)) << 18) + base;
    const float* fb = feat + (((size_t)(b * 96)) << 18) + base;

    // per-warp accumulation channel base pointers (channels wid, wid+32, wid+64)
    const float* fc0 = fb + (((size_t)(wid))      << 18);
    const float* fc1 = fb + (((size_t)(wid + 32)) << 18);
    const float* fc2 = fb + (((size_t)(wid + 64)) << 18);

    // ---------------- Phase 3: iter-0 scores + softmax + centroid update ----------------
    float pd0 = 0.f, pd1 = 0.f, pd2 = 0.f, pd3 = 0.f;
    float an[12];
#pragma unroll
    for (int k = 0; k < 12; k++) an[k] = 0.f;

    for (int ck = 0; ck < 4; ck++) {
        const int bb  = ck & 1;
        const int p   = ck * 1024 + tid;
        const int pix = (p >> 6) * 512 + (p & 63);
        float r0 = 0.f, r1 = 0.f, r2 = 0.f, r3 = 0.f;
        {
            const float* xp = xb + pix;
#pragma unroll 8
            for (int c = 0; c < 32; c++) {
                float v = xp[((size_t)c) << 18];
                float4 g = sh->g4[c];
                r0 = fmaf(v, g.x, r0); r1 = fmaf(v, g.y, r1);
                r2 = fmaf(v, g.z, r2); r3 = fmaf(v, g.w, r3);
            }
            const float* sp = sb + pix;
#pragma unroll 8
            for (int c = 0; c < 31; c++) {
                float v = sp[((size_t)c) << 18];
                float4 g = sh->q4[c];
                r0 = fmaf(v, g.x, r0); r1 = fmaf(v, g.y, r1);
                r2 = fmaf(v, g.z, r2); r3 = fmaf(v, g.w, r3);
            }
        }
        float st0 = 2.f * r0 + C0, st1 = 2.f * r1 + C1;
        float st2 = 2.f * r2 + C2, st3 = 2.f * r3 + C3;
        sh->scst[p] = make_float4(st0, st1, st2, st3);

        float f0 = 0.f, f1_ = 0.f, f2_ = 0.f, f3 = 0.f;
        {
            const float* fp = fb + pix;
#pragma unroll 8
            for (int c = 0; c < 96; c++) {
                float v = fp[((size_t)c) << 18];
                float4 g = sh->cen4[63 + c];
                f0 = fmaf(v, g.x, f0); f1_ = fmaf(v, g.y, f1_);
                f2_ = fmaf(v, g.z, f2_); f3 = fmaf(v, g.w, f3);
            }
        }
        float q0 = st0 + 2.f * f0 - m0;
        float q1 = st1 + 2.f * f1_ - m1;
        float q2 = st2 + 2.f * f2_ - m2;
        float q3 = st3 + 2.f * f3 - m3;
        float mx = fmaxf(fmaxf(q0, q1), fmaxf(q2, q3));
        float e0 = __expf(q0 - mx), e1 = __expf(q1 - mx);
        float e2 = __expf(q2 - mx), e3 = __expf(q3 - mx);
        float inv = 1.f / (e0 + e1 + e2 + e3);
        float a0 = e0 * inv, a1 = e1 * inv, a2 = e2 * inv, a3 = e3 * inv;
        sh->a4[bb][tid] = make_float4(a0, a1, a2, a3);
        pd0 += a0; pd1 += a1; pd2 += a2; pd3 += a3;
        __syncthreads();
        // accumulation: one a4 read shared across the warp's 3 owned channels
        {
            const int coff = ck * 16 * 512 + lane;
#pragma unroll 4
            for (int seg = 0; seg < 32; seg++) {
                const int off = coff + (seg >> 1) * 512 + (seg & 1) * 32;
                float4 a = sh->a4[bb][seg * 32 + lane];
                float v0 = fc0[off], v1 = fc1[off], v2 = fc2[off];
                an[0]  = fmaf(v0, a.x, an[0]);  an[1]  = fmaf(v0, a.y, an[1]);
                an[2]  = fmaf(v0, a.z, an[2]);  an[3]  = fmaf(v0, a.w, an[3]);
                an[4]  = fmaf(v1, a.x, an[4]);  an[5]  = fmaf(v1, a.y, an[5]);
                an[6]  = fmaf(v1, a.z, an[6]);  an[7]  = fmaf(v1, a.w, an[7]);
                an[8]  = fmaf(v2, a.x, an[8]);  an[9]  = fmaf(v2, a.y, an[9]);
                an[10] = fmaf(v2, a.z, an[10]); an[11] = fmaf(v2, a.w, an[11]);
            }
        }
        // no trailing barrier: next chunk uses the other a4 buffer
    }
    pd0 = wredsum(pd0); pd1 = wredsum(pd1); pd2 = wredsum(pd2); pd3 = wredsum(pd3);
    if (lane == 0) {
        atomicAdd(&sh->den[0], pd0); atomicAdd(&sh->den[1], pd1);
        atomicAdd(&sh->den[2], pd2); atomicAdd(&sh->den[3], pd3);
    }
#pragma unroll
    for (int k = 0; k < 12; k++) an[k] = wredsum(an[k]);
    if (lane == 0) {
#pragma unroll
        for (int k = 0; k < 3; k++)
            sh->num4[wid + k * 32] = make_float4(an[k * 4 + 0], an[k * 4 + 1],
                                                 an[k * 4 + 2], an[k * 4 + 3]);
    }
    __syncthreads();
    if (tid < 96) {
        float4 nv = sh->num4[tid];
        float4 o;
        o.x = nv.x / (sh->den[0] + 1e-16f);
        o.y = nv.y / (sh->den[1] + 1e-16f);
        o.z = nv.z / (sh->den[2] + 1e-16f);
        o.w = nv.w / (sh->den[3] + 1e-16f);
        sh->cpf1[tid] = o;
    }
    __syncthreads();
    if (tid < 4) {
        float a = 0.f;
        for (int c = 0; c < 96; c++) { float v = ((const float*)&sh->cpf1[c])[tid]; a = fmaf(v, v, a); }
        sh->n1[tid] = a;
    }
    __syncthreads();

    const float u0 = sh->n1[0], u1 = sh->n1[1], u2 = sh->n1[2], u3 = sh->n1[3];
    const int tloc4 = (f1 * 8 + f2) * 4;
    const int* gtb = gt + (size_t)b * 262144 + base;
    float* spix = out + 57344 + (size_t)b * 262144 + base;

    // ---------------- Phase 4: iter-1, argmax, masked accumulation ----------------
    float pw0 = 0.f, pw1 = 0.f, pw2 = 0.f, pw3 = 0.f;
    float ao[12];
#pragma unroll
    for (int k = 0; k < 12; k++) ao[k] = 0.f;

    for (int ck = 0; ck < 4; ck++) {
        const int bb  = ck & 1;
        const int p   = ck * 1024 + tid;
        const int pix = (p >> 6) * 512 + (p & 63);
        float4 st = sh->scst[p];
        float f0 = 0.f, f1_ = 0.f, f2_ = 0.f, f3 = 0.f;
        const float* fp = fb + pix;
#pragma unroll 8
        for (int c = 0; c < 96; c++) {
            float v = fp[((size_t)c) << 18];
            float4 g = sh->cpf1[c];
            f0 = fmaf(v, g.x, f0); f1_ = fmaf(v, g.y, f1_);
            f2_ = fmaf(v, g.z, f2_); f3 = fmaf(v, g.w, f3);
        }
        float q0 = st.x + 2.f * f0 - u0;
        float q1 = st.y + 2.f * f1_ - u1;
        float q2 = st.z + 2.f * f2_ - u2;
        float q3 = st.w + 2.f * f3 - u3;
        int ss = 0; float best = q0;                 // first-max tie rule (matches jnp.argmax)
        if (q1 > best) { best = q1; ss = 1; }
        if (q2 > best) { best = q2; ss = 2; }
        if (q3 > best) { best = q3; ss = 3; }
        float w = 1.f / (__expf(q0 - best) + __expf(q1 - best)
                       + __expf(q2 - best) + __expf(q3 - best));
        float4 mm;
        mm.x = (ss == 0) ? w : 0.f; mm.y = (ss == 1) ? w : 0.f;
        mm.z = (ss == 2) ? w : 0.f; mm.w = (ss == 3) ? w : 0.f;
        sh->a4[bb][tid] = mm;
        pw0 += mm.x; pw1 += mm.y; pw2 += mm.z; pw3 += mm.w;
        int gv = __ldcs(gtb + pix);
        atomicAdd(&sh->cnt[ss][gv], 1);
        __stcs(spix + pix, (float)(tloc4 + ss));
        __syncthreads();
        {
            const int coff = ck * 16 * 512 + lane;
#pragma unroll 4
            for (int seg = 0; seg < 32; seg++) {
                const int off = coff + (seg >> 1) * 512 + (seg & 1) * 32;
                float4 a = sh->a4[bb][seg * 32 + lane];
                float v0 = fc0[off], v1 = fc1[off], v2 = fc2[off];
                ao[0]  = fmaf(v0, a.x, ao[0]);  ao[1]  = fmaf(v0, a.y, ao[1]);
                ao[2]  = fmaf(v0, a.z, ao[2]);  ao[3]  = fmaf(v0, a.w, ao[3]);
                ao[4]  = fmaf(v1, a.x, ao[4]);  ao[5]  = fmaf(v1, a.y, ao[5]);
                ao[6]  = fmaf(v1, a.z, ao[6]);  ao[7]  = fmaf(v1, a.w, ao[7]);
                ao[8]  = fmaf(v2, a.x, ao[8]);  ao[9]  = fmaf(v2, a.y, ao[9]);
                ao[10] = fmaf(v2, a.z, ao[10]); ao[11] = fmaf(v2, a.w, ao[11]);
            }
        }
    }
    pw0 = wredsum(pw0); pw1 = wredsum(pw1); pw2 = wredsum(pw2); pw3 = wredsum(pw3);
    if (lane == 0) {
        atomicAdd(&sh->wden[0], pw0); atomicAdd(&sh->wden[1], pw1);
        atomicAdd(&sh->wden[2], pw2); atomicAdd(&sh->wden[3], pw3);
    }
#pragma unroll
    for (int k = 0; k < 12; k++) ao[k] = wredsum(ao[k]);
    if (lane == 0) {
#pragma unroll
        for (int k = 0; k < 3; k++)
            sh->onum4[wid + k * 32] = make_float4(ao[k * 4 + 0], ao[k * 4 + 1],
                                                  ao[k * 4 + 2], ao[k * 4 + 3]);
    }
    __syncthreads();

    // ---------------- Phase 5: final writes ----------------
    if (tid < 384) {
        int c = tid >> 2, s = tid & 3;
        float ov = ((const float*)&sh->onum4[c])[s];
        float vc = ((const float*)&sh->cen4[63 + c])[s];
        float res = (ov + vc) / (sh->wden[s] + 1.f);
        out[(size_t)b * 24576 + (size_t)(tloc4 + s) * 96 + c] = res;
    }
    if (tid >= 512 && tid < 576) {
        int t2 = tid - 512; int s = t2 >> 4, cls = t2 & 15;
        out[49152 + (size_t)b * 4096 + (size_t)cls * 256 + tloc4 + s] = (float)sh->cnt[s][cls];
    }
}

extern "C" void kernel_launch(void* const* d_in, const int* in_sizes, int n_in,
                              void* d_out, int out_size) {
    const float* x    = (const float*)d_in[0];
    const float* feat = (const float*)d_in[1];
    const float* sdf  = (const float*)d_in[2];
    const float* Wf   = (const float*)d_in[3];
    const float* bf   = (const float*)d_in[4];
    const float* Wsdf = (const float*)d_in[5];
    const float* bsdf = (const float*)d_in[6];
    const int*   gt   = (const int*)d_in[7];
    float* out = (float*)d_out;

    size_t smem = sizeof(SmemLayout);
    cudaFuncSetAttribute(cluster_kernel, cudaFuncAttributeMaxDynamicSharedMemorySize, (int)smem);
    cluster_kernel<<<128, 1024, smem>>>(x, feat, sdf, Wf, bf, Wsdf, bsdf, gt, out);
}